// round 5
// baseline (speedup 1.0000x reference)
#include <cuda_runtime.h>
#include <cuda_bf16.h>
#include <math.h>
#include <stdint.h>

#define B_     8192
#define OBS_   128
#define LAT_   32
#define NXT_   128
#define E_     8
#define HG_    256
#define H_     256
#define DIN_   (OBS_ + LAT_)   // 160
#define IN1_   (H_ + LAT_)     // 288

// ---------------- device scratch ----------------
__device__ float g_xz [B_ * DIN_];
__device__ float g_g0 [B_ * HG_];
__device__ float g_g1 [B_ * HG_];
__device__ float g_g2 [B_ * HG_];
__device__ float g_h1 [B_ * IN1_];
__device__ float g_h2 [B_ * IN1_];
__device__ float g_coef[B_ * E_];
__device__ float g_w0r[(E_ * DIN_) * H_];
__device__ float g_w1r[(E_ * IN1_) * H_];
__device__ float g_w2r[(E_ * IN1_) * NXT_];
__device__ float g_gv0[3 * DIN_ * HG_];   // gating split weights [3K, N]
__device__ float g_gv1[3 * HG_ * HG_];
__device__ float g_gv2[3 * HG_ * HG_];

// ---------------- helpers ----------------
__device__ __forceinline__ uint32_t smem_u32(const void* p) {
    uint32_t a;
    asm("{ .reg .u64 t; cvta.to.shared.u64 t, %1; cvt.u32.u64 %0, t; }" : "=r"(a) : "l"(p));
    return a;
}
__device__ __forceinline__ uint32_t tf32u(float x) {
    uint32_t r;
    asm("cvt.rna.tf32.f32 %0, %1;" : "=r"(r) : "f"(x));
    return r;
}
#define CP_ASYNC16(dst, src) \
    asm volatile("cp.async.cg.shared.global [%0], [%1], 16;" :: "r"(dst), "l"(src) : "memory")
#define CP_COMMIT() asm volatile("cp.async.commit_group;" ::: "memory")
#define CP_WAIT0()  asm volatile("cp.async.wait_group 0;" ::: "memory")

#define MMA_TF32(d, a, b)                                                          \
    asm volatile("mma.sync.aligned.m16n8k8.row.col.f32.tf32.tf32.f32 "             \
        "{%0,%1,%2,%3}, {%4,%5,%6,%7}, {%8,%9}, {%0,%1,%2,%3};"                    \
        : "+f"((d)[0]), "+f"((d)[1]), "+f"((d)[2]), "+f"((d)[3])                   \
        : "r"((a)[0]), "r"((a)[1]), "r"((a)[2]), "r"((a)[3]),                      \
          "r"((b)[0]), "r"((b)[1]))

// ---------------- pack ----------------
__global__ void pack_kernel(const float* __restrict__ x, const float* __restrict__ z)
{
    int stride = gridDim.x * blockDim.x;
    int idx = blockIdx.x * blockDim.x + threadIdx.x;
    for (int t = idx; t < B_ * DIN_; t += stride) {
        int b = t / DIN_, c = t - b * DIN_;
        g_xz[t] = (c < OBS_) ? x[b * OBS_ + c] : z[b * LAT_ + (c - OBS_)];
    }
    for (int t = idx; t < B_ * LAT_; t += stride) {
        int b = t / LAT_, c = t - b * LAT_;
        float v = z[t];
        g_h1[b * IN1_ + H_ + c] = v;
        g_h2[b * IN1_ + H_ + c] = v;
    }
}

// ---------------- expert weight tf32 rounding (vectorized) ----------------
__global__ void wround_kernel(const float* __restrict__ w, float* __restrict__ wr, int n4)
{
    int stride = gridDim.x * blockDim.x;
    for (int i = blockIdx.x * blockDim.x + threadIdx.x; i < n4; i += stride) {
        float4 v = ((const float4*)w)[i];
        uint4 u;
        u.x = tf32u(v.x); u.y = tf32u(v.y); u.z = tf32u(v.z); u.w = tf32u(v.w);
        ((uint4*)wr)[i] = u;
    }
}

// ---------------- gating weight 3x split: [3K, N] = [Wh; Wh; Wl] ----------------
__global__ void gsplit_kernel(const float* __restrict__ w, float* __restrict__ wv,
                              int K, int N)
{
    int total = 3 * K * N;
    int stride = gridDim.x * blockDim.x;
    for (int idx = blockIdx.x * blockDim.x + threadIdx.x; idx < total; idx += stride) {
        int p = idx / (K * N);
        int rem = idx - p * K * N;
        float a = w[rem];
        uint32_t hi = tf32u(a);
        uint32_t o = (p < 2) ? hi : tf32u(a - __uint_as_float(hi));
        wv[idx] = __uint_as_float(o);
    }
}

// ---------------- gating head + softmax (fp32) ----------------
__global__ __launch_bounds__(256)
void coef_kernel(const float* __restrict__ g2,
                 const float* __restrict__ gw3, const float* __restrict__ gb3)
{
    __shared__ float w_s[HG_ * 9];
    for (int i = threadIdx.x; i < HG_ * E_; i += blockDim.x)
        w_s[(i / E_) * 9 + (i % E_)] = gw3[i];
    __syncthreads();

    int lane   = threadIdx.x & 31;
    int warp   = (blockIdx.x * blockDim.x + threadIdx.x) >> 5;
    int nwarps = (gridDim.x * blockDim.x) >> 5;

    for (int b = warp; b < B_; b += nwarps) {
        float acc[E_] = {};
        for (int i = lane; i < HG_; i += 32) {
            float v = g2[(size_t)b * HG_ + i];
            const float* wr = &w_s[i * 9];
#pragma unroll
            for (int e = 0; e < E_; e++) acc[e] = fmaf(v, wr[e], acc[e]);
        }
#pragma unroll
        for (int e = 0; e < E_; e++)
#pragma unroll
            for (int off = 16; off; off >>= 1)
                acc[e] += __shfl_xor_sync(0xFFFFFFFFu, acc[e], off);
        if (lane == 0) {
            float mx = -1e30f;
#pragma unroll
            for (int e = 0; e < E_; e++) { acc[e] += gb3[e]; mx = fmaxf(mx, acc[e]); }
            float s = 0.f;
#pragma unroll
            for (int e = 0; e < E_; e++) { acc[e] = expf(acc[e] - mx); s += acc[e]; }
            float inv = 1.f / s;
#pragma unroll
            for (int e = 0; e < E_; e++) g_coef[b * E_ + e] = acc[e] * inv;
        }
    }
}

// ---------------- unified tensor GEMM (mma.sync tf32) ----------------
// MODE 0 (expert): C = act([coef*A | coef] @ [[Wr];[bias_E]]),  KTOT = E*IN
// MODE 1 (gating): C = act([Ah|Al|Ah | 1] @ [[Wh];[Wh];[Wl];[bias]]), KTOT = 3*IN
template<int MODE, int IN, int NOUT, int ACT>
__global__ __launch_bounds__(256, 1)
void mma_kernel(const float* __restrict__ A, int lda,
                const float* __restrict__ Wr,
                const float* __restrict__ bias,
                const float* __restrict__ coef,
                float* __restrict__ Cout, int ldc)
{
    constexpr int KTOT = (MODE == 0) ? E_ * IN : 3 * IN;
    constexpr int NT   = KTOT / 32;
    constexpr int NTT  = NT + 1;
    constexpr int ASTR = 36;
    constexpr int BSTR = 136;

    extern __shared__ char smem[];
    float* coef_s = (float*)smem;
    const int OFF_A0 = 4096;
    const int OFF_A1 = OFF_A0 + 128 * ASTR * 4;
    const int OFF_B0 = OFF_A1 + 128 * ASTR * 4;
    const int OFF_B1 = OFF_B0 + 32 * BSTR * 4;
    const int aoff[2] = {OFF_A0, OFF_A1};
    const int boff[2] = {OFF_B0, OFF_B1};

    const uint32_t sb = smem_u32(smem);
    const int tid = threadIdx.x, wid = tid >> 5, lid = tid & 31;
    const int g = lid >> 2, tig = lid & 3;
    const int m0 = blockIdx.y * 128, n0 = blockIdx.x * 128;
    const int rbase = (wid >> 2) * 64;
    const int cbase = (wid & 3) * 32;

    const int arow = tid >> 1;
    const int akq  = (tid & 1) * 16;
    const int bk   = tid >> 3;
    const int bc0  = (tid & 7) * 16;

    if (MODE == 0)
        for (int i = tid; i < 128 * E_; i += 256) coef_s[i] = coef[m0 * E_ + i];
    __syncthreads();

    auto issue_cpasync_B = [&](int t, int buf) {
        const int k0 = t * 32;
#pragma unroll
        for (int i = 0; i < 4; i++) {
            int id  = tid + 256 * i;
            int k   = id >> 5;
            int c4  = (id & 31) * 4;
            uint32_t dst = sb + boff[buf] + (k * BSTR + c4) * 4;
            CP_ASYNC16(dst, Wr + (size_t)(k0 + k) * NOUT + n0 + c4);
        }
        CP_COMMIT();
    };
    auto load_A_regs = [&](int t, float4* pa) {
        const int k0 = t * 32;
        const int i0 = k0 % IN;
        const float* ap = A + (size_t)(m0 + arow) * lda + i0 + akq;
#pragma unroll
        for (int a = 0; a < 4; a++) pa[a] = *(const float4*)(ap + 4 * a);
    };
    auto store_A_smem = [&](int t, int buf, const float4* pa) {
        const int p = (t * 32) / IN;   // MODE0: expert idx; MODE1: pass idx
        float* As = (float*)(smem + aoff[buf]);
        float s = 1.f;
        if (MODE == 0) s = coef_s[arow * E_ + p];
#pragma unroll
        for (int a = 0; a < 4; a++) {
            uint4 u;
            const float* pv = (const float*)&pa[a];
            uint32_t* uu = (uint32_t*)&u;
            if (MODE == 1 && p == 1) {
#pragma unroll
                for (int q = 0; q < 4; q++) {
                    uint32_t hi = tf32u(pv[q]);
                    uu[q] = tf32u(pv[q] - __uint_as_float(hi));
                }
            } else {
#pragma unroll
                for (int q = 0; q < 4; q++) uu[q] = tf32u(pv[q] * s);
            }
            *(uint4*)(As + arow * ASTR + akq + 4 * a) = u;
        }
    };
    auto stage_special = [&](int buf) {
        float* As = (float*)(smem + aoff[buf]);
#pragma unroll
        for (int a = 0; a < 4; a++) {
            uint4 u = {0u, 0u, 0u, 0u};
            uint32_t* uu = (uint32_t*)&u;
#pragma unroll
            for (int q = 0; q < 4; q++) {
                int k = akq + 4 * a + q;
                if (MODE == 0) { if (k < E_) uu[q] = tf32u(coef_s[arow * E_ + k]); }
                else           { if (k == 0) uu[q] = 0x3f800000u; }
            }
            *(uint4*)(As + arow * ASTR + akq + 4 * a) = u;
        }
        float* Bs = (float*)(smem + boff[buf]);
        const int nb = (MODE == 0) ? E_ : 1;
#pragma unroll
        for (int j = 0; j < 16; j += 4) {
            uint4 u = {0u, 0u, 0u, 0u};
            uint32_t* uu = (uint32_t*)&u;
            if (bk < nb)
#pragma unroll
                for (int q = 0; q < 4; q++)
                    uu[q] = tf32u(bias[bk * NOUT + n0 + bc0 + j + q]);
            *(uint4*)(Bs + bk * BSTR + bc0 + j) = u;
        }
    };

    float acc[4][4][4] = {};

    {
        issue_cpasync_B(0, 0);
        float4 pa[4];
        load_A_regs(0, pa);
        store_A_smem(0, 0, pa);
        CP_WAIT0();
    }
    __syncthreads();

    for (int t = 0; t < NTT; t++) {
        const int buf = t & 1;
        const bool hasNext = (t + 1 < NTT);
        const bool nextNormal = (t + 1 < NT);

        float4 pa[4];
        if (hasNext && nextNormal) {
            issue_cpasync_B(t + 1, buf ^ 1);
            load_A_regs(t + 1, pa);
        }
        {
            const uint32_t* Asu = (const uint32_t*)(smem + aoff[buf]);
            const uint32_t* Bsu = (const uint32_t*)(smem + boff[buf]);
#pragma unroll
            for (int k8 = 0; k8 < 4; k8++) {
                uint32_t af[4][4], bf[4][2];
#pragma unroll
                for (int mt = 0; mt < 4; mt++) {
                    const int r0 = rbase + mt * 16 + g;
                    const int kk = k8 * 8 + tig;
                    af[mt][0] = Asu[r0 * ASTR + kk];
                    af[mt][1] = Asu[(r0 + 8) * ASTR + kk];
                    af[mt][2] = Asu[r0 * ASTR + kk + 4];
                    af[mt][3] = Asu[(r0 + 8) * ASTR + kk + 4];
                }
#pragma unroll
                for (int nt = 0; nt < 4; nt++) {
                    const int c0 = cbase + nt * 8 + g;
                    bf[nt][0] = Bsu[(k8 * 8 + tig) * BSTR + c0];
                    bf[nt][1] = Bsu[(k8 * 8 + tig + 4) * BSTR + c0];
                }
#pragma unroll
                for (int mt = 0; mt < 4; mt++)
#pragma unroll
                    for (int nt = 0; nt < 4; nt++)
                        MMA_TF32(acc[mt][nt], af[mt], bf[nt]);
            }
        }
        if (hasNext) {
            if (nextNormal) store_A_smem(t + 1, buf ^ 1, pa);
            else            stage_special(buf ^ 1);
            CP_WAIT0();
        }
        __syncthreads();
    }

#pragma unroll
    for (int mt = 0; mt < 4; mt++) {
        const int r = m0 + rbase + mt * 16 + g;
#pragma unroll
        for (int nt = 0; nt < 4; nt++) {
            const int c = n0 + cbase + nt * 8 + 2 * tig;
            float2 v0, v1;
            v0.x = acc[mt][nt][0]; v0.y = acc[mt][nt][1];
            v1.x = acc[mt][nt][2]; v1.y = acc[mt][nt][3];
            if (ACT == 1) {
                v0.x = (v0.x > 0.f) ? v0.x : expm1f(v0.x);
                v0.y = (v0.y > 0.f) ? v0.y : expm1f(v0.y);
                v1.x = (v1.x > 0.f) ? v1.x : expm1f(v1.x);
                v1.y = (v1.y > 0.f) ? v1.y : expm1f(v1.y);
            }
            *(float2*)(Cout + (size_t)r * ldc + c)       = v0;
            *(float2*)(Cout + (size_t)(r + 8) * ldc + c) = v1;
        }
    }
}

// ---------------- launch ----------------
extern "C" void kernel_launch(void* const* d_in, const int* in_sizes, int n_in,
                              void* d_out, int out_size)
{
    const float* x   = (const float*)d_in[0];
    const float* z   = (const float*)d_in[1];
    const float* gw0 = (const float*)d_in[2];
    const float* gb0 = (const float*)d_in[3];
    const float* gw1 = (const float*)d_in[4];
    const float* gb1 = (const float*)d_in[5];
    const float* gw2 = (const float*)d_in[6];
    const float* gb2 = (const float*)d_in[7];
    const float* gw3 = (const float*)d_in[8];
    const float* gb3 = (const float*)d_in[9];
    const float* w0  = (const float*)d_in[10];
    const float* b0  = (const float*)d_in[11];
    const float* w1  = (const float*)d_in[12];
    const float* b1  = (const float*)d_in[13];
    const float* w2  = (const float*)d_in[14];
    const float* b2  = (const float*)d_in[15];
    float* out = (float*)d_out;

    float *xz, *g0, *g1, *g2, *h1, *h2, *coef, *w0r, *w1r, *w2r, *gv0, *gv1, *gv2;
    cudaGetSymbolAddress((void**)&xz,   g_xz);
    cudaGetSymbolAddress((void**)&g0,   g_g0);
    cudaGetSymbolAddress((void**)&g1,   g_g1);
    cudaGetSymbolAddress((void**)&g2,   g_g2);
    cudaGetSymbolAddress((void**)&h1,   g_h1);
    cudaGetSymbolAddress((void**)&h2,   g_h2);
    cudaGetSymbolAddress((void**)&coef, g_coef);
    cudaGetSymbolAddress((void**)&w0r,  g_w0r);
    cudaGetSymbolAddress((void**)&w1r,  g_w1r);
    cudaGetSymbolAddress((void**)&w2r,  g_w2r);
    cudaGetSymbolAddress((void**)&gv0,  g_gv0);
    cudaGetSymbolAddress((void**)&gv1,  g_gv1);
    cudaGetSymbolAddress((void**)&gv2,  g_gv2);

    const int smem_bytes = 4096 + 2 * (128 * 36 * 4) + 2 * (32 * 136 * 4);  // 75776
    cudaFuncSetAttribute(mma_kernel<1, DIN_, HG_, 1>, cudaFuncAttributeMaxDynamicSharedMemorySize, smem_bytes);
    cudaFuncSetAttribute(mma_kernel<1, HG_,  HG_, 1>, cudaFuncAttributeMaxDynamicSharedMemorySize, smem_bytes);
    cudaFuncSetAttribute(mma_kernel<0, DIN_, H_,  1>, cudaFuncAttributeMaxDynamicSharedMemorySize, smem_bytes);
    cudaFuncSetAttribute(mma_kernel<0, IN1_, H_,  1>, cudaFuncAttributeMaxDynamicSharedMemorySize, smem_bytes);
    cudaFuncSetAttribute(mma_kernel<0, IN1_, NXT_,0>, cudaFuncAttributeMaxDynamicSharedMemorySize, smem_bytes);

    pack_kernel<<<1024, 256>>>(x, z);
    gsplit_kernel<<<512, 256>>>(gw0, gv0, DIN_, HG_);
    gsplit_kernel<<<768, 256>>>(gw1, gv1, HG_, HG_);
    gsplit_kernel<<<768, 256>>>(gw2, gv2, HG_, HG_);

    // gating MLP on tensor cores (3x tf32 split) — 5th launch = profiled
    mma_kernel<1, DIN_, HG_, 1><<<dim3(HG_/128, B_/128), 256, smem_bytes>>>(
        xz, DIN_, gv0, gb0, nullptr, g0, HG_);
    mma_kernel<1, HG_, HG_, 1><<<dim3(HG_/128, B_/128), 256, smem_bytes>>>(
        g0, HG_, gv1, gb1, nullptr, g1, HG_);
    mma_kernel<1, HG_, HG_, 1><<<dim3(HG_/128, B_/128), 256, smem_bytes>>>(
        g1, HG_, gv2, gb2, nullptr, g2, HG_);
    coef_kernel<<<64, 256>>>(g2, gw3, gb3);

    wround_kernel<<<640,  256>>>(w0, w0r, E_ * DIN_ * H_ / 4);
    wround_kernel<<<1152, 256>>>(w1, w1r, E_ * IN1_ * H_ / 4);
    wround_kernel<<<576,  256>>>(w2, w2r, E_ * IN1_ * NXT_ / 4);

    mma_kernel<0, DIN_, H_, 1><<<dim3(H_/128, B_/128), 256, smem_bytes>>>(
        xz, DIN_, w0r, b0, coef, h1, IN1_);
    mma_kernel<0, IN1_, H_, 1><<<dim3(H_/128, B_/128), 256, smem_bytes>>>(
        h1, IN1_, w1r, b1, coef, h2, IN1_);
    mma_kernel<0, IN1_, NXT_, 0><<<dim3(NXT_/128, B_/128), 256, smem_bytes>>>(
        h2, IN1_, w2r, b2, coef, out, NXT_);
}

// round 6
// speedup vs baseline: 1.0661x; 1.0661x over previous
#include <cuda_runtime.h>
#include <cuda_bf16.h>
#include <math.h>
#include <stdint.h>

#define B_     8192
#define OBS_   128
#define LAT_   32
#define NXT_   128
#define E_     8
#define HG_    256
#define H_     256
#define DIN_   (OBS_ + LAT_)   // 160
#define IN1_   (H_ + LAT_)     // 288

// ---------------- device scratch ----------------
__device__ float g_xz [B_ * DIN_];
__device__ float g_g0 [B_ * HG_];
__device__ float g_g1 [B_ * HG_];
__device__ float g_g2 [B_ * HG_];
__device__ float g_h1 [B_ * IN1_];
__device__ float g_h2 [B_ * IN1_];
__device__ float g_coef[B_ * E_];
__device__ float g_w0r[(E_ * DIN_) * H_];
__device__ float g_w1r[(E_ * IN1_) * H_];
__device__ float g_w2r[(E_ * IN1_) * NXT_];
__device__ float g_gv0[3 * DIN_ * HG_];
__device__ float g_gv1[3 * HG_ * HG_];
__device__ float g_gv2[3 * HG_ * HG_];

// ---------------- helpers ----------------
__device__ __forceinline__ uint32_t smem_u32(const void* p) {
    uint32_t a;
    asm("{ .reg .u64 t; cvta.to.shared.u64 t, %1; cvt.u32.u64 %0, t; }" : "=r"(a) : "l"(p));
    return a;
}
__device__ __forceinline__ uint32_t tf32u(float x) {
    uint32_t r;
    asm("cvt.rna.tf32.f32 %0, %1;" : "=r"(r) : "f"(x));
    return r;
}
#define CP_ASYNC16(dst, src) \
    asm volatile("cp.async.cg.shared.global [%0], [%1], 16;" :: "r"(dst), "l"(src) : "memory")
#define CP_COMMIT() asm volatile("cp.async.commit_group;" ::: "memory")
#define CP_WAIT0()  asm volatile("cp.async.wait_group 0;" ::: "memory")
#define CP_WAIT1()  asm volatile("cp.async.wait_group 1;" ::: "memory")

#define MMA_TF32(d, a, b)                                                          \
    asm volatile("mma.sync.aligned.m16n8k8.row.col.f32.tf32.tf32.f32 "             \
        "{%0,%1,%2,%3}, {%4,%5,%6,%7}, {%8,%9}, {%0,%1,%2,%3};"                    \
        : "+f"((d)[0]), "+f"((d)[1]), "+f"((d)[2]), "+f"((d)[3])                   \
        : "r"((a)[0]), "r"((a)[1]), "r"((a)[2]), "r"((a)[3]),                      \
          "r"((b)[0]), "r"((b)[1]))

// ---------------- pack ----------------
__global__ void pack_kernel(const float* __restrict__ x, const float* __restrict__ z)
{
    int stride = gridDim.x * blockDim.x;
    int idx = blockIdx.x * blockDim.x + threadIdx.x;
    for (int t = idx; t < B_ * DIN_; t += stride) {
        int b = t / DIN_, c = t - b * DIN_;
        g_xz[t] = (c < OBS_) ? x[b * OBS_ + c] : z[b * LAT_ + (c - OBS_)];
    }
    for (int t = idx; t < B_ * LAT_; t += stride) {
        int b = t / LAT_, c = t - b * LAT_;
        float v = z[t];
        g_h1[b * IN1_ + H_ + c] = v;
        g_h2[b * IN1_ + H_ + c] = v;
    }
}

// ---------------- fused weight prep: tf32-round experts + 3x-split gating ----------------
__device__ __forceinline__ void wround_seg(const float* w, float* wr, int n4,
                                           int idx, int stride)
{
    for (int i = idx; i < n4; i += stride) {
        float4 v = ((const float4*)w)[i];
        uint4 u;
        u.x = tf32u(v.x); u.y = tf32u(v.y); u.z = tf32u(v.z); u.w = tf32u(v.w);
        ((uint4*)wr)[i] = u;
    }
}
__device__ __forceinline__ void gsplit_seg(const float* w, float* wv, int kn,
                                           int idx, int stride)
{
    for (int i = idx; i < kn; i += stride) {
        float a = w[i];
        uint32_t hi = tf32u(a);
        uint32_t lo = tf32u(a - __uint_as_float(hi));
        wv[i] = __uint_as_float(hi);
        wv[kn + i] = __uint_as_float(hi);
        wv[2 * kn + i] = __uint_as_float(lo);
    }
}
__global__ void wprep_kernel(const float* w0, const float* w1, const float* w2,
                             const float* gw0, const float* gw1, const float* gw2)
{
    int idx = blockIdx.x * blockDim.x + threadIdx.x;
    int stride = gridDim.x * blockDim.x;
    wround_seg(w0, g_w0r, E_ * DIN_ * H_ / 4, idx, stride);
    wround_seg(w1, g_w1r, E_ * IN1_ * H_ / 4, idx, stride);
    wround_seg(w2, g_w2r, E_ * IN1_ * NXT_ / 4, idx, stride);
    gsplit_seg(gw0, g_gv0, DIN_ * HG_, idx, stride);
    gsplit_seg(gw1, g_gv1, HG_ * HG_, idx, stride);
    gsplit_seg(gw2, g_gv2, HG_ * HG_, idx, stride);
}

// ---------------- gating head + softmax (fp32) ----------------
__global__ __launch_bounds__(256)
void coef_kernel(const float* __restrict__ g2,
                 const float* __restrict__ gw3, const float* __restrict__ gb3)
{
    __shared__ float w_s[HG_ * 9];
    for (int i = threadIdx.x; i < HG_ * E_; i += blockDim.x)
        w_s[(i / E_) * 9 + (i % E_)] = gw3[i];
    __syncthreads();
    int lane = threadIdx.x & 31;
    int warp = (blockIdx.x * blockDim.x + threadIdx.x) >> 5;
    int nwarps = (gridDim.x * blockDim.x) >> 5;
    for (int b = warp; b < B_; b += nwarps) {
        float acc[E_] = {};
        for (int i = lane; i < HG_; i += 32) {
            float v = g2[(size_t)b * HG_ + i];
            const float* wr = &w_s[i * 9];
#pragma unroll
            for (int e = 0; e < E_; e++) acc[e] = fmaf(v, wr[e], acc[e]);
        }
#pragma unroll
        for (int e = 0; e < E_; e++)
#pragma unroll
            for (int off = 16; off; off >>= 1)
                acc[e] += __shfl_xor_sync(0xFFFFFFFFu, acc[e], off);
        if (lane == 0) {
            float mx = -1e30f;
#pragma unroll
            for (int e = 0; e < E_; e++) { acc[e] += gb3[e]; mx = fmaxf(mx, acc[e]); }
            float s = 0.f;
#pragma unroll
            for (int e = 0; e < E_; e++) { acc[e] = expf(acc[e] - mx); s += acc[e]; }
            float inv = 1.f / s;
#pragma unroll
            for (int e = 0; e < E_; e++) g_coef[b * E_ + e] = acc[e] * inv;
        }
    }
}

// ---------------- pipelined tensor GEMM (mma.sync tf32) ----------------
// MODE 0 (expert): C = act([coef*A | coef] @ [[Wr];[bias_E]])
// MODE 1 (gating): C = act([Ah|Al|Ah | 1] @ [[Wh];[Wh];[Wl];[bias]])
// BM=128, BK=32. B: 3-stage cp.async pipeline. A: reg-prefetch + double buffer.
template<int MODE, int IN, int NOUT, int BN, int ACT>
__global__ __launch_bounds__(256, 1)
void mma_kernel(const float* __restrict__ A, int lda,
                const float* __restrict__ Wr,
                const float* __restrict__ bias,
                const float* __restrict__ coef,
                float* __restrict__ Cout, int ldc)
{
    constexpr int KTOT = (MODE == 0) ? E_ * IN : 3 * IN;
    constexpr int NT   = KTOT / 32;
    constexpr int NTT  = NT + 1;
    constexpr int ASTR = 36;
    constexpr int BSTR = BN + 8;
    constexpr int WCOLS = BN / 32;              // warp col groups (4 or 2)
    constexpr int WROWS = 8 / WCOLS;            // warp row groups (2 or 4)
    constexpr int MT    = 128 / (WROWS * 16);   // m16 tiles per warp (4 or 2)
    constexpr int ABYTES = 128 * ASTR * 4;
    constexpr int BBYTES = 32 * BSTR * 4;

    extern __shared__ char smem[];
    float* coef_s = (float*)smem;
    const int offA[2] = {4096, 4096 + ABYTES};
    const int offB[3] = {4096 + 2 * ABYTES, 4096 + 2 * ABYTES + BBYTES,
                         4096 + 2 * ABYTES + 2 * BBYTES};
    const uint32_t sb = smem_u32(smem);

    const int tid = threadIdx.x, wid = tid >> 5, lid = tid & 31;
    const int g = lid >> 2, tig = lid & 3;
    const int m0 = blockIdx.y * 128, n0 = blockIdx.x * BN;
    const int rbase = (wid / WCOLS) * (MT * 16);
    const int cbase = (wid % WCOLS) * 32;
    const int arow = tid >> 1, akq = (tid & 1) * 16;

    if (MODE == 0)
        for (int i = tid; i < 128 * E_; i += 256) coef_s[i] = coef[m0 * E_ + i];
    __syncthreads();

    auto cpB = [&](int t, int buf) {
#pragma unroll
        for (int i = 0; i < BN / 32; i++) {
            int id = tid + 256 * i;
            int k = id / (BN / 4), c4 = (id % (BN / 4)) * 4;
            CP_ASYNC16(sb + offB[buf] + (k * BSTR + c4) * 4,
                       Wr + (size_t)(t * 32 + k) * NOUT + n0 + c4);
        }
        CP_COMMIT();
    };
    auto ldA = [&](int t, float4* pa) {
        const int i0 = (t * 32) % IN;
        const float* ap = A + (size_t)(m0 + arow) * lda + i0 + akq;
#pragma unroll
        for (int a = 0; a < 4; a++) pa[a] = *(const float4*)(ap + 4 * a);
    };
    auto stA = [&](int t, int buf, const float4* pa) {
        const int p = (t * 32) / IN;
        float* As = (float*)(smem + offA[buf]);
        float s = 1.f;
        if (MODE == 0) s = coef_s[arow * E_ + p];
#pragma unroll
        for (int a = 0; a < 4; a++) {
            uint4 u;
            const float* pv = (const float*)&pa[a];
            uint32_t* uu = (uint32_t*)&u;
            if (MODE == 1 && p == 1) {
#pragma unroll
                for (int q = 0; q < 4; q++) {
                    uint32_t hi = tf32u(pv[q]);
                    uu[q] = tf32u(pv[q] - __uint_as_float(hi));
                }
            } else {
#pragma unroll
                for (int q = 0; q < 4; q++) uu[q] = tf32u(pv[q] * s);
            }
            *(uint4*)(As + arow * ASTR + akq + 4 * a) = u;
        }
    };
    auto stSpec = [&](int abuf, int bbuf) {
        float* As = (float*)(smem + offA[abuf]);
#pragma unroll
        for (int a = 0; a < 4; a++) {
            uint4 u = {0u, 0u, 0u, 0u};
            uint32_t* uu = (uint32_t*)&u;
#pragma unroll
            for (int q = 0; q < 4; q++) {
                int k = akq + 4 * a + q;
                if (MODE == 0) { if (k < E_) uu[q] = tf32u(coef_s[arow * E_ + k]); }
                else           { if (k == 0) uu[q] = 0x3f800000u; }
            }
            *(uint4*)(As + arow * ASTR + akq + 4 * a) = u;
        }
        float* Bs = (float*)(smem + offB[bbuf]);
        const int nb = (MODE == 0) ? E_ : 1;
        const int bk = tid / (BN / 16), bc0 = (tid % (BN / 16)) * 16;
        if (bk < 32)
#pragma unroll
            for (int j = 0; j < 16; j += 4) {
                uint4 u = {0u, 0u, 0u, 0u};
                uint32_t* uu = (uint32_t*)&u;
                if (bk < nb)
#pragma unroll
                    for (int q = 0; q < 4; q++)
                        uu[q] = tf32u(bias[bk * NOUT + n0 + bc0 + j + q]);
                *(uint4*)(Bs + bk * BSTR + bc0 + j) = u;
            }
    };

    float acc[MT][4][4] = {};

    // prologue: B(0), B(1) in flight; A(0) staged
    cpB(0, 0);
    if (NT > 1) cpB(1, 1);
    float4 pa[4];
    ldA(0, pa);
    stA(0, 0, pa);
    CP_WAIT1();
    __syncthreads();

    for (int t = 0; t < NTT; t++) {
        const int abuf = t & 1, bbuf = t % 3;
        if (t + 2 < NT) cpB(t + 2, (t + 2) % 3);
        const bool nxt = (t + 1 < NTT), nrm = (t + 1 < NT);
        if (nxt && nrm) ldA(t + 1, pa);

        {
            const uint32_t* Asu = (const uint32_t*)(smem + offA[abuf]);
            const uint32_t* Bsu = (const uint32_t*)(smem + offB[bbuf]);
#pragma unroll
            for (int k8 = 0; k8 < 4; k8++) {
                uint32_t af[MT][4], bf[4][2];
#pragma unroll
                for (int mt = 0; mt < MT; mt++) {
                    const int r0 = rbase + mt * 16 + g;
                    const int kk = k8 * 8 + tig;
                    af[mt][0] = Asu[r0 * ASTR + kk];
                    af[mt][1] = Asu[(r0 + 8) * ASTR + kk];
                    af[mt][2] = Asu[r0 * ASTR + kk + 4];
                    af[mt][3] = Asu[(r0 + 8) * ASTR + kk + 4];
                }
#pragma unroll
                for (int nt = 0; nt < 4; nt++) {
                    const int c0 = cbase + nt * 8 + g;
                    bf[nt][0] = Bsu[(k8 * 8 + tig) * BSTR + c0];
                    bf[nt][1] = Bsu[(k8 * 8 + tig + 4) * BSTR + c0];
                }
#pragma unroll
                for (int mt = 0; mt < MT; mt++)
#pragma unroll
                    for (int nt = 0; nt < 4; nt++)
                        MMA_TF32(acc[mt][nt], af[mt], bf[nt]);
            }
        }

        if (nxt) {
            if (nrm) stA(t + 1, abuf ^ 1, pa);
            else     stSpec(abuf ^ 1, (t + 1) % 3);
        }
        if (t + 1 < NT) CP_WAIT1(); else CP_WAIT0();
        __syncthreads();
    }

#pragma unroll
    for (int mt = 0; mt < MT; mt++) {
        const int r = m0 + rbase + mt * 16 + g;
#pragma unroll
        for (int nt = 0; nt < 4; nt++) {
            const int c = n0 + cbase + nt * 8 + 2 * tig;
            float2 v0, v1;
            v0.x = acc[mt][nt][0]; v0.y = acc[mt][nt][1];
            v1.x = acc[mt][nt][2]; v1.y = acc[mt][nt][3];
            if (ACT == 1) {
                v0.x = (v0.x > 0.f) ? v0.x : expm1f(v0.x);
                v0.y = (v0.y > 0.f) ? v0.y : expm1f(v0.y);
                v1.x = (v1.x > 0.f) ? v1.x : expm1f(v1.x);
                v1.y = (v1.y > 0.f) ? v1.y : expm1f(v1.y);
            }
            *(float2*)(Cout + (size_t)r * ldc + c)       = v0;
            *(float2*)(Cout + (size_t)(r + 8) * ldc + c) = v1;
        }
    }
}

// ---------------- launch ----------------
extern "C" void kernel_launch(void* const* d_in, const int* in_sizes, int n_in,
                              void* d_out, int out_size)
{
    const float* x   = (const float*)d_in[0];
    const float* z   = (const float*)d_in[1];
    const float* gw0 = (const float*)d_in[2];
    const float* gb0 = (const float*)d_in[3];
    const float* gw1 = (const float*)d_in[4];
    const float* gb1 = (const float*)d_in[5];
    const float* gw2 = (const float*)d_in[6];
    const float* gb2 = (const float*)d_in[7];
    const float* gw3 = (const float*)d_in[8];
    const float* gb3 = (const float*)d_in[9];
    const float* w0  = (const float*)d_in[10];
    const float* b0  = (const float*)d_in[11];
    const float* w1  = (const float*)d_in[12];
    const float* b1  = (const float*)d_in[13];
    const float* w2  = (const float*)d_in[14];
    const float* b2  = (const float*)d_in[15];
    float* out = (float*)d_out;

    float *xz, *g0, *g1, *g2, *h1, *h2, *coef, *w0r, *w1r, *w2r, *gv0, *gv1, *gv2;
    cudaGetSymbolAddress((void**)&xz, g_xz);
    cudaGetSymbolAddress((void**)&g0, g_g0);
    cudaGetSymbolAddress((void**)&g1, g_g1);
    cudaGetSymbolAddress((void**)&g2, g_g2);
    cudaGetSymbolAddress((void**)&h1, g_h1);
    cudaGetSymbolAddress((void**)&h2, g_h2);
    cudaGetSymbolAddress((void**)&coef, g_coef);
    cudaGetSymbolAddress((void**)&w0r, g_w0r);
    cudaGetSymbolAddress((void**)&w1r, g_w1r);
    cudaGetSymbolAddress((void**)&w2r, g_w2r);
    cudaGetSymbolAddress((void**)&gv0, g_gv0);
    cudaGetSymbolAddress((void**)&gv1, g_gv1);
    cudaGetSymbolAddress((void**)&gv2, g_gv2);

    const int ABYTES = 128 * 36 * 4;
    const int SM128 = 4096 + 2 * ABYTES + 3 * (32 * 136 * 4);  // 93184
    const int SM64  = 4096 + 2 * ABYTES + 3 * (32 * 72 * 4);   // 68608
    cudaFuncSetAttribute(mma_kernel<1, DIN_, HG_, 128, 1>, cudaFuncAttributeMaxDynamicSharedMemorySize, SM128);
    cudaFuncSetAttribute(mma_kernel<1, HG_,  HG_, 128, 1>, cudaFuncAttributeMaxDynamicSharedMemorySize, SM128);
    cudaFuncSetAttribute(mma_kernel<0, DIN_, H_,  128, 1>, cudaFuncAttributeMaxDynamicSharedMemorySize, SM128);
    cudaFuncSetAttribute(mma_kernel<0, IN1_, H_,  128, 1>, cudaFuncAttributeMaxDynamicSharedMemorySize, SM128);
    cudaFuncSetAttribute(mma_kernel<0, IN1_, NXT_, 64, 0>, cudaFuncAttributeMaxDynamicSharedMemorySize, SM64);

    pack_kernel<<<1024, 256>>>(x, z);
    wprep_kernel<<<296, 256>>>(w0, w1, w2, gw0, gw1, gw2);

    mma_kernel<1, DIN_, HG_, 128, 1><<<dim3(HG_/128, B_/128), 256, SM128>>>(
        xz, DIN_, gv0, gb0, nullptr, g0, HG_);
    mma_kernel<1, HG_, HG_, 128, 1><<<dim3(HG_/128, B_/128), 256, SM128>>>(
        g0, HG_, gv1, gb1, nullptr, g1, HG_);
    mma_kernel<1, HG_, HG_, 128, 1><<<dim3(HG_/128, B_/128), 256, SM128>>>(
        g1, HG_, gv2, gb2, nullptr, g2, HG_);
    coef_kernel<<<128, 256>>>(g2, gw3, gb3);

    mma_kernel<0, DIN_, H_, 128, 1><<<dim3(H_/128, B_/128), 256, SM128>>>(
        xz, DIN_, w0r, b0, coef, h1, IN1_);
    mma_kernel<0, IN1_, H_, 128, 1><<<dim3(H_/128, B_/128), 256, SM128>>>(
        h1, IN1_, w1r, b1, coef, h2, IN1_);
    mma_kernel<0, IN1_, NXT_, 64, 0><<<dim3(NXT_/64, B_/128), 256, SM64>>>(
        h2, IN1_, w2r, b2, coef, out, NXT_);
}

// round 7
// speedup vs baseline: 1.1659x; 1.0937x over previous
#include <cuda_runtime.h>
#include <cuda_bf16.h>
#include <math.h>
#include <stdint.h>

#define B_     8192
#define OBS_   128
#define LAT_   32
#define NXT_   128
#define E_     8
#define HG_    256
#define H_     256
#define DIN_   (OBS_ + LAT_)   // 160
#define IN1_   (H_ + LAT_)     // 288

// ---------------- device scratch ----------------
__device__ float g_xz [B_ * DIN_];
__device__ float g_g0 [B_ * HG_];
__device__ float g_g1 [B_ * HG_];
__device__ float g_g2 [B_ * HG_];
__device__ float g_h1 [B_ * IN1_];
__device__ float g_h2 [B_ * IN1_];
__device__ float g_coef[B_ * E_];
__device__ float g_w0r[(E_ * DIN_) * H_];
__device__ float g_w1r[(E_ * IN1_) * H_];
__device__ float g_w2r[(E_ * IN1_) * NXT_];
__device__ float g_gv0[3 * DIN_ * HG_];
__device__ float g_gv1[3 * HG_ * HG_];
__device__ float g_gv2[3 * HG_ * HG_];

// ---------------- helpers ----------------
__device__ __forceinline__ uint32_t smem_u32(const void* p) {
    uint32_t a;
    asm("{ .reg .u64 t; cvta.to.shared.u64 t, %1; cvt.u32.u64 %0, t; }" : "=r"(a) : "l"(p));
    return a;
}
__device__ __forceinline__ uint32_t tf32u(float x) {
    uint32_t r;
    asm("cvt.rna.tf32.f32 %0, %1;" : "=r"(r) : "f"(x));
    return r;
}
#define CP_ASYNC16(dst, src) \
    asm volatile("cp.async.cg.shared.global [%0], [%1], 16;" :: "r"(dst), "l"(src) : "memory")
#define CP_COMMIT() asm volatile("cp.async.commit_group;" ::: "memory")
#define CP_WAIT0()  asm volatile("cp.async.wait_group 0;" ::: "memory")
#define CP_WAIT1()  asm volatile("cp.async.wait_group 1;" ::: "memory")

#define MMA_TF32(d, a, b)                                                          \
    asm volatile("mma.sync.aligned.m16n8k8.row.col.f32.tf32.tf32.f32 "             \
        "{%0,%1,%2,%3}, {%4,%5,%6,%7}, {%8,%9}, {%0,%1,%2,%3};"                    \
        : "+f"((d)[0]), "+f"((d)[1]), "+f"((d)[2]), "+f"((d)[3])                   \
        : "r"((a)[0]), "r"((a)[1]), "r"((a)[2]), "r"((a)[3]),                      \
          "r"((b)[0]), "r"((b)[1]))

// ---------------- pack ----------------
__global__ void pack_kernel(const float* __restrict__ x, const float* __restrict__ z)
{
    int stride = gridDim.x * blockDim.x;
    int idx = blockIdx.x * blockDim.x + threadIdx.x;
    for (int t = idx; t < B_ * DIN_; t += stride) {
        int b = t / DIN_, c = t - b * DIN_;
        g_xz[t] = (c < OBS_) ? x[b * OBS_ + c] : z[b * LAT_ + (c - OBS_)];
    }
    for (int t = idx; t < B_ * LAT_; t += stride) {
        int b = t / LAT_, c = t - b * LAT_;
        float v = z[t];
        g_h1[b * IN1_ + H_ + c] = v;
        g_h2[b * IN1_ + H_ + c] = v;
    }
}

// ---------------- fused weight prep ----------------
__device__ __forceinline__ void wround_seg(const float* w, float* wr, int n4,
                                           int idx, int stride)
{
    for (int i = idx; i < n4; i += stride) {
        float4 v = ((const float4*)w)[i];
        uint4 u;
        u.x = tf32u(v.x); u.y = tf32u(v.y); u.z = tf32u(v.z); u.w = tf32u(v.w);
        ((uint4*)wr)[i] = u;
    }
}
__device__ __forceinline__ void gsplit_seg(const float* w, float* wv, int kn,
                                           int idx, int stride)
{
    for (int i = idx; i < kn; i += stride) {
        float a = w[i];
        uint32_t hi = tf32u(a);
        uint32_t lo = tf32u(a - __uint_as_float(hi));
        wv[i] = __uint_as_float(hi);
        wv[kn + i] = __uint_as_float(hi);
        wv[2 * kn + i] = __uint_as_float(lo);
    }
}
__global__ void wprep_kernel(const float* w0, const float* w1, const float* w2,
                             const float* gw0, const float* gw1, const float* gw2)
{
    int idx = blockIdx.x * blockDim.x + threadIdx.x;
    int stride = gridDim.x * blockDim.x;
    wround_seg(w0, g_w0r, E_ * DIN_ * H_ / 4, idx, stride);
    wround_seg(w1, g_w1r, E_ * IN1_ * H_ / 4, idx, stride);
    wround_seg(w2, g_w2r, E_ * IN1_ * NXT_ / 4, idx, stride);
    gsplit_seg(gw0, g_gv0, DIN_ * HG_, idx, stride);
    gsplit_seg(gw1, g_gv1, HG_ * HG_, idx, stride);
    gsplit_seg(gw2, g_gv2, HG_ * HG_, idx, stride);
}

// ---------------- gating head + softmax (fp32) ----------------
__global__ __launch_bounds__(256)
void coef_kernel(const float* __restrict__ g2,
                 const float* __restrict__ gw3, const float* __restrict__ gb3)
{
    __shared__ float w_s[HG_ * 9];
    for (int i = threadIdx.x; i < HG_ * E_; i += blockDim.x)
        w_s[(i / E_) * 9 + (i % E_)] = gw3[i];
    __syncthreads();
    int lane = threadIdx.x & 31;
    int warp = (blockIdx.x * blockDim.x + threadIdx.x) >> 5;
    int nwarps = (gridDim.x * blockDim.x) >> 5;
    for (int b = warp; b < B_; b += nwarps) {
        float acc[E_] = {};
        for (int i = lane; i < HG_; i += 32) {
            float v = g2[(size_t)b * HG_ + i];
            const float* wr = &w_s[i * 9];
#pragma unroll
            for (int e = 0; e < E_; e++) acc[e] = fmaf(v, wr[e], acc[e]);
        }
#pragma unroll
        for (int e = 0; e < E_; e++)
#pragma unroll
            for (int off = 16; off; off >>= 1)
                acc[e] += __shfl_xor_sync(0xFFFFFFFFu, acc[e], off);
        if (lane == 0) {
            float mx = -1e30f;
#pragma unroll
            for (int e = 0; e < E_; e++) { acc[e] += gb3[e]; mx = fmaxf(mx, acc[e]); }
            float s = 0.f;
#pragma unroll
            for (int e = 0; e < E_; e++) { acc[e] = expf(acc[e] - mx); s += acc[e]; }
            float inv = 1.f / s;
#pragma unroll
            for (int e = 0; e < E_; e++) g_coef[b * E_ + e] = acc[e] * inv;
        }
    }
}

// ---------------- pipelined tensor GEMM, BM=64, 2 CTAs/SM ----------------
// MODE 0 (expert): C = act([coef*A | coef] @ [[Wr];[bias_E]])
// MODE 1 (gating): C = act([Ah|Al|Ah | 1] @ [[Wh];[Wh];[Wl];[bias]])
template<int MODE, int IN, int NOUT, int BN, int ACT>
__global__ __launch_bounds__(256, 2)
void mma_kernel(const float* __restrict__ A, int lda,
                const float* __restrict__ Wr,
                const float* __restrict__ bias,
                const float* __restrict__ coef,
                float* __restrict__ Cout, int ldc)
{
    constexpr int BM   = 64;
    constexpr int KTOT = (MODE == 0) ? E_ * IN : 3 * IN;
    constexpr int NT   = KTOT / 32;
    constexpr int NTT  = NT + 1;
    constexpr int ASTR = 36;
    constexpr int BSTR = BN + 8;
    constexpr int WCOLS = BN / 32;               // 4 or 2
    constexpr int WROWS = 8 / WCOLS;             // 2 or 4
    constexpr int MT    = BM / (WROWS * 16);     // 2 or 1
    constexpr int ABYTES = BM * ASTR * 4;
    constexpr int BBYTES = 32 * BSTR * 4;

    extern __shared__ char smem[];
    float* coef_s = (float*)smem;
    const int offA[2] = {4096, 4096 + ABYTES};
    const int offB[3] = {4096 + 2 * ABYTES, 4096 + 2 * ABYTES + BBYTES,
                         4096 + 2 * ABYTES + 2 * BBYTES};
    const uint32_t sb = smem_u32(smem);

    const int tid = threadIdx.x, wid = tid >> 5, lid = tid & 31;
    const int g = lid >> 2, tig = lid & 3;
    const int m0 = blockIdx.y * BM, n0 = blockIdx.x * BN;
    const int rbase = (wid / WCOLS) * (MT * 16);
    const int cbase = (wid % WCOLS) * 32;
    const int arow = tid >> 2, ak8 = (tid & 3) * 8;

    if (MODE == 0)
        for (int i = tid; i < BM * E_; i += 256) coef_s[i] = coef[m0 * E_ + i];
    __syncthreads();

    auto cpB = [&](int t, int buf) {
#pragma unroll
        for (int i = 0; i < BN / 32; i++) {
            int id = tid + 256 * i;
            int k = id / (BN / 4), c4 = (id % (BN / 4)) * 4;
            CP_ASYNC16(sb + offB[buf] + (k * BSTR + c4) * 4,
                       Wr + (size_t)(t * 32 + k) * NOUT + n0 + c4);
        }
        CP_COMMIT();
    };
    auto ldA = [&](int t, float4* pa) {
        const int i0 = (t * 32) % IN;
        const float* ap = A + (size_t)(m0 + arow) * lda + i0 + ak8;
        pa[0] = *(const float4*)ap;
        pa[1] = *(const float4*)(ap + 4);
    };
    auto stA = [&](int t, int buf, const float4* pa) {
        const int p = (t * 32) / IN;
        float* As = (float*)(smem + offA[buf]);
        float s = 1.f;
        if (MODE == 0) s = coef_s[arow * E_ + p];
#pragma unroll
        for (int a = 0; a < 2; a++) {
            uint4 u;
            const float* pv = (const float*)&pa[a];
            uint32_t* uu = (uint32_t*)&u;
            if (MODE == 1 && p == 1) {
#pragma unroll
                for (int q = 0; q < 4; q++) {
                    uint32_t hi = tf32u(pv[q]);
                    uu[q] = tf32u(pv[q] - __uint_as_float(hi));
                }
            } else {
#pragma unroll
                for (int q = 0; q < 4; q++) uu[q] = tf32u(pv[q] * s);
            }
            *(uint4*)(As + arow * ASTR + ak8 + 4 * a) = u;
        }
    };
    auto stSpec = [&](int abuf, int bbuf) {
        float* As = (float*)(smem + offA[abuf]);
#pragma unroll
        for (int a = 0; a < 2; a++) {
            uint4 u = {0u, 0u, 0u, 0u};
            uint32_t* uu = (uint32_t*)&u;
#pragma unroll
            for (int q = 0; q < 4; q++) {
                int k = ak8 + 4 * a + q;
                if (MODE == 0) { if (k < E_) uu[q] = tf32u(coef_s[arow * E_ + k]); }
                else           { if (k == 0) uu[q] = 0x3f800000u; }
            }
            *(uint4*)(As + arow * ASTR + ak8 + 4 * a) = u;
        }
        float* Bs = (float*)(smem + offB[bbuf]);
        const int nb = (MODE == 0) ? E_ : 1;
        const int bk = tid / (BN / 16), bc0 = (tid % (BN / 16)) * 16;
        if (bk < 32)
#pragma unroll
            for (int j = 0; j < 16; j += 4) {
                uint4 u = {0u, 0u, 0u, 0u};
                uint32_t* uu = (uint32_t*)&u;
                if (bk < nb)
#pragma unroll
                    for (int q = 0; q < 4; q++)
                        uu[q] = tf32u(bias[bk * NOUT + n0 + bc0 + j + q]);
                *(uint4*)(Bs + bk * BSTR + bc0 + j) = u;
            }
    };

    float acc[MT][4][4] = {};

    cpB(0, 0);
    if (NT > 1) cpB(1, 1);
    float4 pa[2];
    ldA(0, pa);
    stA(0, 0, pa);
    CP_WAIT1();
    __syncthreads();

    for (int t = 0; t < NTT; t++) {
        const int abuf = t & 1, bbuf = t % 3;
        if (t + 2 < NT) cpB(t + 2, (t + 2) % 3);
        const bool nxt = (t + 1 < NTT), nrm = (t + 1 < NT);
        if (nxt && nrm) ldA(t + 1, pa);

        {
            const uint32_t* Asu = (const uint32_t*)(smem + offA[abuf]);
            const uint32_t* Bsu = (const uint32_t*)(smem + offB[bbuf]);
#pragma unroll
            for (int k8 = 0; k8 < 4; k8++) {
                uint32_t af[MT][4], bf[4][2];
#pragma unroll
                for (int mt = 0; mt < MT; mt++) {
                    const int r0 = rbase + mt * 16 + g;
                    const int kk = k8 * 8 + tig;
                    af[mt][0] = Asu[r0 * ASTR + kk];
                    af[mt][1] = Asu[(r0 + 8) * ASTR + kk];
                    af[mt][2] = Asu[r0 * ASTR + kk + 4];
                    af[mt][3] = Asu[(r0 + 8) * ASTR + kk + 4];
                }
#pragma unroll
                for (int nt = 0; nt < 4; nt++) {
                    const int c0 = cbase + nt * 8 + g;
                    bf[nt][0] = Bsu[(k8 * 8 + tig) * BSTR + c0];
                    bf[nt][1] = Bsu[(k8 * 8 + tig + 4) * BSTR + c0];
                }
#pragma unroll
                for (int mt = 0; mt < MT; mt++)
#pragma unroll
                    for (int nt = 0; nt < 4; nt++)
                        MMA_TF32(acc[mt][nt], af[mt], bf[nt]);
            }
        }

        if (nxt) {
            if (nrm) stA(t + 1, abuf ^ 1, pa);
            else     stSpec(abuf ^ 1, (t + 1) % 3);
        }
        if (t + 1 < NT) CP_WAIT1(); else CP_WAIT0();
        __syncthreads();
    }

#pragma unroll
    for (int mt = 0; mt < MT; mt++) {
        const int r = m0 + rbase + mt * 16 + g;
#pragma unroll
        for (int nt = 0; nt < 4; nt++) {
            const int c = n0 + cbase + nt * 8 + 2 * tig;
            float2 v0, v1;
            v0.x = acc[mt][nt][0]; v0.y = acc[mt][nt][1];
            v1.x = acc[mt][nt][2]; v1.y = acc[mt][nt][3];
            if (ACT == 1) {
                v0.x = (v0.x > 0.f) ? v0.x : expm1f(v0.x);
                v0.y = (v0.y > 0.f) ? v0.y : expm1f(v0.y);
                v1.x = (v1.x > 0.f) ? v1.x : expm1f(v1.x);
                v1.y = (v1.y > 0.f) ? v1.y : expm1f(v1.y);
            }
            *(float2*)(Cout + (size_t)r * ldc + c)       = v0;
            *(float2*)(Cout + (size_t)(r + 8) * ldc + c) = v1;
        }
    }
}

// ---------------- launch ----------------
extern "C" void kernel_launch(void* const* d_in, const int* in_sizes, int n_in,
                              void* d_out, int out_size)
{
    const float* x   = (const float*)d_in[0];
    const float* z   = (const float*)d_in[1];
    const float* gw0 = (const float*)d_in[2];
    const float* gb0 = (const float*)d_in[3];
    const float* gw1 = (const float*)d_in[4];
    const float* gb1 = (const float*)d_in[5];
    const float* gw2 = (const float*)d_in[6];
    const float* gb2 = (const float*)d_in[7];
    const float* gw3 = (const float*)d_in[8];
    const float* gb3 = (const float*)d_in[9];
    const float* w0  = (const float*)d_in[10];
    const float* b0  = (const float*)d_in[11];
    const float* w1  = (const float*)d_in[12];
    const float* b1  = (const float*)d_in[13];
    const float* w2  = (const float*)d_in[14];
    const float* b2  = (const float*)d_in[15];
    float* out = (float*)d_out;

    float *xz, *g0, *g1, *g2, *h1, *h2, *coef, *w0r, *w1r, *w2r, *gv0, *gv1, *gv2;
    cudaGetSymbolAddress((void**)&xz, g_xz);
    cudaGetSymbolAddress((void**)&g0, g_g0);
    cudaGetSymbolAddress((void**)&g1, g_g1);
    cudaGetSymbolAddress((void**)&g2, g_g2);
    cudaGetSymbolAddress((void**)&h1, g_h1);
    cudaGetSymbolAddress((void**)&h2, g_h2);
    cudaGetSymbolAddress((void**)&coef, g_coef);
    cudaGetSymbolAddress((void**)&w0r, g_w0r);
    cudaGetSymbolAddress((void**)&w1r, g_w1r);
    cudaGetSymbolAddress((void**)&w2r, g_w2r);
    cudaGetSymbolAddress((void**)&gv0, g_gv0);
    cudaGetSymbolAddress((void**)&gv1, g_gv1);
    cudaGetSymbolAddress((void**)&gv2, g_gv2);

    const int ABYTES = 64 * 36 * 4;
    const int SM128 = 4096 + 2 * ABYTES + 3 * (32 * 136 * 4);  // 74752
    const int SM64  = 4096 + 2 * ABYTES + 3 * (32 * 72 * 4);   // 50176
    cudaFuncSetAttribute(mma_kernel<1, DIN_, HG_, 128, 1>, cudaFuncAttributeMaxDynamicSharedMemorySize, SM128);
    cudaFuncSetAttribute(mma_kernel<1, HG_,  HG_, 128, 1>, cudaFuncAttributeMaxDynamicSharedMemorySize, SM128);
    cudaFuncSetAttribute(mma_kernel<0, DIN_, H_,  128, 1>, cudaFuncAttributeMaxDynamicSharedMemorySize, SM128);
    cudaFuncSetAttribute(mma_kernel<0, IN1_, H_,  128, 1>, cudaFuncAttributeMaxDynamicSharedMemorySize, SM128);
    cudaFuncSetAttribute(mma_kernel<0, IN1_, NXT_, 64, 0>, cudaFuncAttributeMaxDynamicSharedMemorySize, SM64);

    pack_kernel<<<1024, 256>>>(x, z);
    wprep_kernel<<<296, 256>>>(w0, w1, w2, gw0, gw1, gw2);

    mma_kernel<1, DIN_, HG_, 128, 1><<<dim3(HG_/128, B_/64), 256, SM128>>>(
        xz, DIN_, gv0, gb0, nullptr, g0, HG_);
    mma_kernel<1, HG_, HG_, 128, 1><<<dim3(HG_/128, B_/64), 256, SM128>>>(
        g0, HG_, gv1, gb1, nullptr, g1, HG_);
    mma_kernel<1, HG_, HG_, 128, 1><<<dim3(HG_/128, B_/64), 256, SM128>>>(
        g1, HG_, gv2, gb2, nullptr, g2, HG_);
    coef_kernel<<<128, 256>>>(g2, gw3, gb3);

    mma_kernel<0, DIN_, H_, 128, 1><<<dim3(H_/128, B_/64), 256, SM128>>>(
        xz, DIN_, w0r, b0, coef, h1, IN1_);
    mma_kernel<0, IN1_, H_, 128, 1><<<dim3(H_/128, B_/64), 256, SM128>>>(
        h1, IN1_, w1r, b1, coef, h2, IN1_);
    mma_kernel<0, IN1_, NXT_, 64, 0><<<dim3(NXT_/64, B_/64), 256, SM64>>>(
        h2, IN1_, w2r, b2, coef, out, NXT_);
}